// round 4
// baseline (speedup 1.0000x reference)
#include <cuda_runtime.h>
#include <cuda_bf16.h>
#include <stdint.h>
#include <math.h>

#define NE    32
#define DH    1024
#define DI    768
#define NT    2048
#define TOPK  8
#define NP    (NT * TOPK)   // 16384 (token, expert) pairs
#define KC    64            // K elems per chunk (64 bf16 = 128 B = SW128 row)

// ---------------- scratch (static device globals) ---------------------------
__device__ int   g_cnt[NE];
__device__ int   g_cur[NE];
__device__ int   g_off[NE + 1];
__device__ int   g_tok[NP];
__device__ float g_wt[NP];
__device__ int   g_map[NP];
__device__ __align__(16) __nv_bfloat16 g_h_hi[(size_t)NP * DI];
__device__ __align__(16) __nv_bfloat16 g_h_lo[(size_t)NP * DI];
__device__ __align__(16) float         g_d[(size_t)NP * DH];

// ---------------- helpers ------------------------------------------------------
#define SWZ(o) ((o) ^ (((o) >> 3) & 0x70))

__device__ __forceinline__ uint32_t smem_u32(const void* p) {
    uint32_t a;
    asm("{ .reg .u64 t; cvta.to.shared.u64 t, %1; cvt.u32.u64 %0, t; }"
        : "=r"(a) : "l"(p));
    return a;
}

__device__ __forceinline__ void ldm4(uint32_t* r, uint32_t a) {
    asm volatile("ldmatrix.sync.aligned.m8n8.x4.shared.b16 {%0,%1,%2,%3}, [%4];"
        : "=r"(r[0]), "=r"(r[1]), "=r"(r[2]), "=r"(r[3]) : "r"(a));
}
__device__ __forceinline__ void mma_bf(float* d, const uint32_t* a, const uint32_t* b) {
    asm volatile("mma.sync.aligned.m16n8k16.row.col.f32.bf16.bf16.f32 "
        "{%0,%1,%2,%3}, {%4,%5,%6,%7}, {%8,%9}, {%0,%1,%2,%3};"
        : "+f"(d[0]), "+f"(d[1]), "+f"(d[2]), "+f"(d[3])
        : "r"(a[0]), "r"(a[1]), "r"(a[2]), "r"(a[3]), "r"(b[0]), "r"(b[1]));
}
__device__ __forceinline__ void cpa16(uint32_t dst, const void* src, uint32_t sz) {
    asm volatile("cp.async.cg.shared.global [%0], [%1], 16, %2;"
                 :: "r"(dst), "l"(src), "r"(sz) : "memory");
}
#define CP_COMMIT() asm volatile("cp.async.commit_group;" ::: "memory")
#define CP_WAIT0()  asm volatile("cp.async.wait_group 0;" ::: "memory")

// 8 fp32 -> packed bf16 hi/lo (2 uint4) via bf16x2 cvt
__device__ __forceinline__ void split8(const float* v, uint4& H, uint4& L) {
    uint32_t h[4], l[4];
    #pragma unroll
    for (int p = 0; p < 4; p++) {
        float a = v[2 * p], b = v[2 * p + 1];
        __nv_bfloat162 hb = __floats2bfloat162_rn(a, b);
        float2 hf = __bfloat1622float2(hb);
        __nv_bfloat162 lb = __floats2bfloat162_rn(a - hf.x, b - hf.y);
        h[p] = *reinterpret_cast<uint32_t*>(&hb);
        l[p] = *reinterpret_cast<uint32_t*>(&lb);
    }
    H = make_uint4(h[0], h[1], h[2], h[3]);
    L = make_uint4(l[0], l[1], l[2], l[3]);
}

__device__ __forceinline__ void split1(float v, uint16_t* h, uint16_t* l) {
    __nv_bfloat16 hb = __float2bfloat16_rn(v);
    *h = __bfloat16_as_ushort(hb);
    *l = __bfloat16_as_ushort(__float2bfloat16_rn(v - __bfloat162float(hb)));
}

// Fill one 128x64 bf16 smem tile pair (hi/lo) from fp32 global rows.
// Each thread owns row frow, 32-col half fcol (4 x 16B segments).
__device__ __forceinline__ void fill_f32_tile(char* th, char* tl,
        const float* rowp, int k0, int frow, int fcol, bool valid) {
    #pragma unroll
    for (int j = 0; j < 4; j++) {
        float v[8];
        if (valid) {
            float4 a0 = *(const float4*)(rowp + k0 + fcol + j * 8);
            float4 a1 = *(const float4*)(rowp + k0 + fcol + j * 8 + 4);
            v[0] = a0.x; v[1] = a0.y; v[2] = a0.z; v[3] = a0.w;
            v[4] = a1.x; v[5] = a1.y; v[6] = a1.z; v[7] = a1.w;
        } else {
            #pragma unroll
            for (int q = 0; q < 8; q++) v[q] = 0.f;
        }
        uint4 H, L;
        split8(v, H, L);
        uint32_t s = SWZ((uint32_t)(frow * 128 + fcol * 2 + j * 16));
        *(uint4*)(th + s) = H;
        *(uint4*)(tl + s) = L;
    }
}

// ---------------- setup kernels ----------------------------------------------
__global__ void k_zero() {
    int i = threadIdx.x;
    if (i < NE) { g_cnt[i] = 0; g_cur[i] = 0; }
}
__global__ void k_count(const int* __restrict__ sel) {
    int i = blockIdx.x * 256 + threadIdx.x;
    if (i < NP) atomicAdd(&g_cnt[sel[i]], 1);
}
__global__ void k_scan() {
    if (threadIdx.x == 0) {
        int acc = 0; g_off[0] = 0;
        for (int e = 0; e < NE; e++) { acc += g_cnt[e]; g_off[e + 1] = acc; }
    }
}
__global__ void k_scatter(const int* __restrict__ sel, const float* __restrict__ rw) {
    int i = blockIdx.x * 256 + threadIdx.x;
    if (i < NP) {
        int e = sel[i];
        int p = g_off[e] + atomicAdd(&g_cur[e], 1);
        g_tok[p] = i / TOPK;
        g_wt[p]  = rw[i];
        g_map[i] = p;
    }
}

// ---------------- GEMM 1: gate + up, SwiGLU epilogue --------------------------
// per-stage: A_hi A_lo G_hi G_lo U_hi U_lo (16KB each) -> 96KB; 2 stages.
#define GU_STAGE 98304
#define GU_SMEM  (2 * GU_STAGE + 64)
#define GU_NCH   (DH / KC)   // 16

__global__ __launch_bounds__(256, 1)
void k_gateup(const float* __restrict__ hs, const float* __restrict__ gate,
              const float* __restrict__ up) {
    const int e    = blockIdx.z;
    const int base = g_off[e];
    const int cnt  = g_off[e + 1] - base;
    const int rowStart = blockIdx.y * 128;
    if (rowStart >= cnt) return;
    const int iStart = blockIdx.x * 128;

    extern __shared__ __align__(1024) char sm[];

    const int tid = threadIdx.x;
    const int wid = tid >> 5, lane = tid & 31;
    const int frow = tid >> 1, fcol = (tid & 1) * 32;

    const int grow = rowStart + frow;
    const bool av  = (grow < cnt);
    const int tok  = av ? g_tok[base + grow] : 0;
    const float* ap  = hs + (size_t)tok * DH;
    const float* gp  = gate + ((size_t)e * DI + iStart + frow) * DH;
    const float* upp = up   + ((size_t)e * DI + iStart + frow) * DH;

    const int wm = wid & 3, wn = wid >> 2;
    float accg[2][8][4], accu[2][8][4];
    #pragma unroll
    for (int a = 0; a < 2; a++)
        #pragma unroll
        for (int b = 0; b < 8; b++)
            #pragma unroll
            for (int q = 0; q < 4; q++) { accg[a][b][q] = 0.f; accu[a][b][q] = 0.f; }

    const int a_r = (lane & 15);
    const int a_k = (lane >> 4) * 16;
    const int b_r = ((lane >> 4) & 1) * 8 + (lane & 7);
    const int b_k = ((lane >> 3) & 1) * 16;

    // prologue: fill stage 0 with chunk 0
    {
        char* st = sm;
        fill_f32_tile(st,         st + 16384, ap,  0, frow, fcol, av);
        fill_f32_tile(st + 32768, st + 49152, gp,  0, frow, fcol, true);
        fill_f32_tile(st + 65536, st + 81920, upp, 0, frow, fcol, true);
    }
    __syncthreads();

    for (int c = 0; c < GU_NCH; c++) {
        // fill next chunk into the other stage (overlaps with this chunk's MMAs
        // issued by other warps; protected by the trailing sync)
        if (c + 1 < GU_NCH) {
            char* st = sm + ((c + 1) & 1) * GU_STAGE;
            const int k0 = (c + 1) * KC;
            fill_f32_tile(st,         st + 16384, ap,  k0, frow, fcol, av);
            fill_f32_tile(st + 32768, st + 49152, gp,  k0, frow, fcol, true);
            fill_f32_tile(st + 65536, st + 81920, upp, k0, frow, fcol, true);
        }

        const uint32_t sb = smem_u32(sm + (c & 1) * GU_STAGE);
        const uint32_t sAh = sb, sAl = sb + 16384;
        const uint32_t sGh = sb + 32768, sGl = sb + 49152;
        const uint32_t sUh = sb + 65536, sUl = sb + 81920;

        #pragma unroll
        for (int ks = 0; ks < 4; ks++) {
            uint32_t ah[2][4], al[2][4];
            #pragma unroll
            for (int mi = 0; mi < 2; mi++) {
                uint32_t off = SWZ((uint32_t)((wm * 32 + mi * 16 + a_r) * 128 + ks * 32 + a_k));
                ldm4(ah[mi], sAh + off);
                ldm4(al[mi], sAl + off);
            }
            #pragma unroll
            for (int njp = 0; njp < 4; njp++) {
                uint32_t boff = SWZ((uint32_t)((wn * 64 + njp * 16 + b_r) * 128 + ks * 32 + b_k));
                uint32_t bh[4], bl[4];
                ldm4(bh, sGh + boff);
                ldm4(bl, sGl + boff);
                #pragma unroll
                for (int mi = 0; mi < 2; mi++)
                    #pragma unroll
                    for (int j = 0; j < 2; j++) {
                        mma_bf(accg[mi][njp * 2 + j], ah[mi], &bh[j * 2]);
                        mma_bf(accg[mi][njp * 2 + j], ah[mi], &bl[j * 2]);
                        mma_bf(accg[mi][njp * 2 + j], al[mi], &bh[j * 2]);
                    }
                ldm4(bh, sUh + boff);
                ldm4(bl, sUl + boff);
                #pragma unroll
                for (int mi = 0; mi < 2; mi++)
                    #pragma unroll
                    for (int j = 0; j < 2; j++) {
                        mma_bf(accu[mi][njp * 2 + j], ah[mi], &bh[j * 2]);
                        mma_bf(accu[mi][njp * 2 + j], ah[mi], &bl[j * 2]);
                        mma_bf(accu[mi][njp * 2 + j], al[mi], &bh[j * 2]);
                    }
            }
        }
        __syncthreads();
    }

    // epilogue: h = w * silu(g) * u, split to bf16 hi/lo in g_h
    #pragma unroll
    for (int mi = 0; mi < 2; mi++) {
        #pragma unroll
        for (int h2 = 0; h2 < 2; h2++) {
            const int r = rowStart + wm * 32 + mi * 16 + (lane >> 2) + h2 * 8;
            if (r < cnt) {
                const float w = g_wt[base + r];
                const size_t rb = (size_t)(base + r) * DI + iStart;
                #pragma unroll
                for (int nj = 0; nj < 8; nj++) {
                    const int col = wn * 64 + nj * 8 + (lane & 3) * 2;
                    float g0 = accg[mi][nj][h2 * 2 + 0], g1 = accg[mi][nj][h2 * 2 + 1];
                    float u0 = accu[mi][nj][h2 * 2 + 0], u1 = accu[mi][nj][h2 * 2 + 1];
                    float h0 = w * (g0 / (1.f + __expf(-g0))) * u0;
                    float h1 = w * (g1 / (1.f + __expf(-g1))) * u1;
                    uint16_t a0, b0, a1, b1;
                    split1(h0, &a0, &b0); split1(h1, &a1, &b1);
                    *(uint32_t*)&g_h_hi[rb + col] = a0 | ((uint32_t)a1 << 16);
                    *(uint32_t*)&g_h_lo[rb + col] = b0 | ((uint32_t)b1 << 16);
                }
            }
        }
    }
}

// ---------------- GEMM 2: down projection -> g_d ------------------------------
// per-stage: A_hi A_lo B_hi B_lo (16KB each) -> 64KB; 2 stages.
#define DN_STAGE 65536
#define DN_SMEM  (2 * DN_STAGE + 64)
#define DN_NCH   (DI / KC)   // 12

__global__ __launch_bounds__(256, 1)
void k_down(const float* __restrict__ down) {
    const int e    = blockIdx.z;
    const int base = g_off[e];
    const int cnt  = g_off[e + 1] - base;
    const int rowStart = blockIdx.y * 128;
    if (rowStart >= cnt) return;
    const int hStart = blockIdx.x * 128;

    extern __shared__ __align__(1024) char sm[];

    const int tid = threadIdx.x;
    const int wid = tid >> 5, lane = tid & 31;
    const int frow = tid >> 1, fcol = (tid & 1) * 32;

    const int grow = rowStart + frow;
    const bool av  = (grow < cnt);
    const uint32_t asz = av ? 16u : 0u;
    const __nv_bfloat16* ah = g_h_hi + (size_t)(av ? base + grow : 0) * DI + fcol;
    const __nv_bfloat16* al = g_h_lo + (size_t)(av ? base + grow : 0) * DI + fcol;
    const float* bp = down + ((size_t)e * DH + hStart + frow) * DI;

    const int wm = wid & 3, wn = wid >> 2;
    float acc[2][8][4];
    #pragma unroll
    for (int a = 0; a < 2; a++)
        #pragma unroll
        for (int b = 0; b < 8; b++)
            #pragma unroll
            for (int q = 0; q < 4; q++) acc[a][b][q] = 0.f;

    const int a_r = (lane & 15);
    const int a_k = (lane >> 4) * 16;
    const int b_r = ((lane >> 4) & 1) * 8 + (lane & 7);
    const int b_k = ((lane >> 3) & 1) * 16;

    // A-tile via cp.async (bf16 source), B-tile via fp32 split.
    auto fill = [&](int c, char* st) {
        const int k0 = c * KC;
        const uint32_t dA = smem_u32(st);
        #pragma unroll
        for (int j = 0; j < 4; j++) {
            uint32_t s = SWZ((uint32_t)(frow * 128 + fcol * 2 + j * 16));
            cpa16(dA + s,         ah + k0 + j * 8, asz);
            cpa16(dA + 16384 + s, al + k0 + j * 8, asz);
        }
        fill_f32_tile(st + 32768, st + 49152, bp, k0, frow, fcol, true);
    };

    fill(0, sm);
    CP_COMMIT();
    CP_WAIT0();
    __syncthreads();

    for (int c = 0; c < DN_NCH; c++) {
        if (c + 1 < DN_NCH) fill(c + 1, sm + ((c + 1) & 1) * DN_STAGE);
        CP_COMMIT();

        const uint32_t sb = smem_u32(sm + (c & 1) * DN_STAGE);
        const uint32_t sAh = sb, sAl = sb + 16384;
        const uint32_t sBh = sb + 32768, sBl = sb + 49152;

        #pragma unroll
        for (int ks = 0; ks < 4; ks++) {
            uint32_t ahf[2][4], alf[2][4];
            #pragma unroll
            for (int mi = 0; mi < 2; mi++) {
                uint32_t off = SWZ((uint32_t)((wm * 32 + mi * 16 + a_r) * 128 + ks * 32 + a_k));
                ldm4(ahf[mi], sAh + off);
                ldm4(alf[mi], sAl + off);
            }
            #pragma unroll
            for (int njp = 0; njp < 4; njp++) {
                uint32_t boff = SWZ((uint32_t)((wn * 64 + njp * 16 + b_r) * 128 + ks * 32 + b_k));
                uint32_t bh[4], bl[4];
                ldm4(bh, sBh + boff);
                ldm4(bl, sBl + boff);
                #pragma unroll
                for (int mi = 0; mi < 2; mi++)
                    #pragma unroll
                    for (int j = 0; j < 2; j++) {
                        mma_bf(acc[mi][njp * 2 + j], ahf[mi], &bh[j * 2]);
                        mma_bf(acc[mi][njp * 2 + j], ahf[mi], &bl[j * 2]);
                        mma_bf(acc[mi][njp * 2 + j], alf[mi], &bh[j * 2]);
                    }
            }
        }
        CP_WAIT0();
        __syncthreads();
    }

    #pragma unroll
    for (int mi = 0; mi < 2; mi++) {
        #pragma unroll
        for (int h2 = 0; h2 < 2; h2++) {
            const int r = rowStart + wm * 32 + mi * 16 + (lane >> 2) + h2 * 8;
            if (r < cnt) {
                float* dp = &g_d[(size_t)(base + r) * DH + hStart];
                #pragma unroll
                for (int nj = 0; nj < 8; nj++) {
                    const int col = wn * 64 + nj * 8 + (lane & 3) * 2;
                    float2 o;
                    o.x = acc[mi][nj][h2 * 2 + 0];
                    o.y = acc[mi][nj][h2 * 2 + 1];
                    *(float2*)(dp + col) = o;
                }
            }
        }
    }
}

// ---------------- deterministic combine ---------------------------------------
__global__ void k_combine(float* __restrict__ out) {
    const int t = blockIdx.x;
    __shared__ int ps[TOPK];
    if (threadIdx.x < TOPK) ps[threadIdx.x] = g_map[t * TOPK + threadIdx.x];
    __syncthreads();
    const int h = threadIdx.x * 4;
    float4 s = make_float4(0.f, 0.f, 0.f, 0.f);
    #pragma unroll
    for (int k = 0; k < TOPK; k++) {
        float4 v = *(const float4*)&g_d[(size_t)ps[k] * DH + h];
        s.x += v.x; s.y += v.y; s.z += v.z; s.w += v.w;
    }
    *(float4*)&out[(size_t)t * DH + h] = s;
}

// ---------------- launch -------------------------------------------------------
extern "C" void kernel_launch(void* const* d_in, const int* in_sizes, int n_in,
                              void* d_out, int out_size) {
    const float* hs   = (const float*)d_in[0];
    const float* rw   = (const float*)d_in[1];
    const int*   sel  = (const int*)  d_in[2];
    const float* gate = (const float*)d_in[3];
    const float* up   = (const float*)d_in[4];
    const float* down = (const float*)d_in[5];
    float* out = (float*)d_out;

    k_zero<<<1, 32>>>();
    k_count<<<(NP + 255) / 256, 256>>>(sel);
    k_scan<<<1, 1>>>();
    k_scatter<<<(NP + 255) / 256, 256>>>(sel, rw);

    cudaFuncSetAttribute(k_gateup, cudaFuncAttributeMaxDynamicSharedMemorySize, GU_SMEM);
    cudaFuncSetAttribute(k_down,   cudaFuncAttributeMaxDynamicSharedMemorySize, DN_SMEM);

    // 16 token-tiles per expert covers cnt <= 2048 (expected 512)
    dim3 gg(DI / 128, 16, NE);   // (6, 16, 32)
    k_gateup<<<gg, 256, GU_SMEM>>>(hs, gate, up);

    dim3 gd(DH / 128, 16, NE);   // (8, 16, 32)
    k_down<<<gd, 256, DN_SMEM>>>(down);

    k_combine<<<NT, 256>>>(out);
}

// round 5
// speedup vs baseline: 1.2239x; 1.2239x over previous
#include <cuda_runtime.h>
#include <cuda_bf16.h>
#include <stdint.h>
#include <math.h>

#define NE    32
#define DH    1024
#define DI    768
#define NT    2048
#define TOPK  8
#define NP    (NT * TOPK)   // 16384 (token, expert) pairs
#define KC    64            // K elems per chunk (64 bf16 = 128 B = SW128 row)
#define NW    (NE * DI * DH)   // elems per weight tensor (25.2M)

// ---------------- scratch (static device globals) ---------------------------
__device__ int   g_cnt[NE];
__device__ int   g_cur[NE];
__device__ int   g_off[NE + 1];
__device__ int   g_tok[NP];
__device__ float g_wt[NP];
__device__ int   g_map[NP];
__device__ __align__(16) __nv_bfloat16 g_h_hi[(size_t)NP * DI];
__device__ __align__(16) __nv_bfloat16 g_h_lo[(size_t)NP * DI];
__device__ __align__(16) float         g_d[(size_t)NP * DH];
// pre-split weights + activations (hi/lo bf16)
__device__ __align__(16) __nv_bfloat16 w_g_hi[NW], w_g_lo[NW];
__device__ __align__(16) __nv_bfloat16 w_u_hi[NW], w_u_lo[NW];
__device__ __align__(16) __nv_bfloat16 w_d_hi[NW], w_d_lo[NW];
__device__ __align__(16) __nv_bfloat16 hs_hi[NT * DH], hs_lo[NT * DH];

// ---------------- helpers ------------------------------------------------------
#define SWZ(o) ((o) ^ (((o) >> 3) & 0x70))

__device__ __forceinline__ uint32_t smem_u32(const void* p) {
    uint32_t a;
    asm("{ .reg .u64 t; cvta.to.shared.u64 t, %1; cvt.u32.u64 %0, t; }"
        : "=r"(a) : "l"(p));
    return a;
}
__device__ __forceinline__ void ldm4(uint32_t* r, uint32_t a) {
    asm volatile("ldmatrix.sync.aligned.m8n8.x4.shared.b16 {%0,%1,%2,%3}, [%4];"
        : "=r"(r[0]), "=r"(r[1]), "=r"(r[2]), "=r"(r[3]) : "r"(a));
}
__device__ __forceinline__ void mma_bf(float* d, const uint32_t* a, const uint32_t* b) {
    asm volatile("mma.sync.aligned.m16n8k16.row.col.f32.bf16.bf16.f32 "
        "{%0,%1,%2,%3}, {%4,%5,%6,%7}, {%8,%9}, {%0,%1,%2,%3};"
        : "+f"(d[0]), "+f"(d[1]), "+f"(d[2]), "+f"(d[3])
        : "r"(a[0]), "r"(a[1]), "r"(a[2]), "r"(a[3]), "r"(b[0]), "r"(b[1]));
}
__device__ __forceinline__ void cpa16(uint32_t dst, const void* src, uint32_t sz) {
    asm volatile("cp.async.cg.shared.global [%0], [%1], 16, %2;"
                 :: "r"(dst), "l"(src), "r"(sz) : "memory");
}
#define CP_COMMIT() asm volatile("cp.async.commit_group;" ::: "memory")
#define CP_WAIT(n)  asm volatile("cp.async.wait_group %0;" :: "n"(n) : "memory")

// 8 fp32 -> packed bf16 hi/lo (2 uint4)
__device__ __forceinline__ void split8(const float* v, uint4& H, uint4& L) {
    uint32_t h[4], l[4];
    #pragma unroll
    for (int p = 0; p < 4; p++) {
        float a = v[2 * p], b = v[2 * p + 1];
        __nv_bfloat162 hb = __floats2bfloat162_rn(a, b);
        float2 hf = __bfloat1622float2(hb);
        __nv_bfloat162 lb = __floats2bfloat162_rn(a - hf.x, b - hf.y);
        h[p] = *reinterpret_cast<uint32_t*>(&hb);
        l[p] = *reinterpret_cast<uint32_t*>(&lb);
    }
    H = make_uint4(h[0], h[1], h[2], h[3]);
    L = make_uint4(l[0], l[1], l[2], l[3]);
}
__device__ __forceinline__ void split1(float v, uint16_t* h, uint16_t* l) {
    __nv_bfloat16 hb = __float2bfloat16_rn(v);
    *h = __bfloat16_as_ushort(hb);
    *l = __bfloat16_as_ushort(__float2bfloat16_rn(v - __bfloat162float(hb)));
}

// ---------------- pre-convert: fp32 -> bf16 hi/lo ------------------------------
__global__ __launch_bounds__(256) void k_cvt(const float* __restrict__ src,
        __nv_bfloat16* __restrict__ hi, __nv_bfloat16* __restrict__ lo, int n8) {
    int i = blockIdx.x * 256 + threadIdx.x;
    if (i >= n8) return;
    float v[8];
    float4 a0 = *((const float4*)src + i * 2);
    float4 a1 = *((const float4*)src + i * 2 + 1);
    v[0] = a0.x; v[1] = a0.y; v[2] = a0.z; v[3] = a0.w;
    v[4] = a1.x; v[5] = a1.y; v[6] = a1.z; v[7] = a1.w;
    uint4 H, L;
    split8(v, H, L);
    *(uint4*)(hi + (size_t)i * 8) = H;
    *(uint4*)(lo + (size_t)i * 8) = L;
}

// ---------------- setup kernels ----------------------------------------------
__global__ void k_zero() {
    int i = threadIdx.x;
    if (i < NE) { g_cnt[i] = 0; g_cur[i] = 0; }
}
__global__ void k_count(const int* __restrict__ sel) {
    int i = blockIdx.x * 256 + threadIdx.x;
    if (i < NP) atomicAdd(&g_cnt[sel[i]], 1);
}
__global__ void k_scan() {
    if (threadIdx.x == 0) {
        int acc = 0; g_off[0] = 0;
        for (int e = 0; e < NE; e++) { acc += g_cnt[e]; g_off[e + 1] = acc; }
    }
}
__global__ void k_scatter(const int* __restrict__ sel, const float* __restrict__ rw) {
    int i = blockIdx.x * 256 + threadIdx.x;
    if (i < NP) {
        int e = sel[i];
        int p = g_off[e] + atomicAdd(&g_cur[e], 1);
        g_tok[p] = i / TOPK;
        g_wt[p]  = rw[i];
        g_map[i] = p;
    }
}

// ---------------- GEMM 1: gate + up, SwiGLU epilogue --------------------------
// stage: A_hi A_lo G_hi G_lo U_hi U_lo (16KB each) = 96KB; 2 stages (cp.async)
#define TILEB    16384
#define GU_STAGE (6 * TILEB)
#define GU_SMEM  (2 * GU_STAGE + 64)
#define GU_NCH   (DH / KC)   // 16

__global__ __launch_bounds__(256, 1)
void k_gateup(const float* __restrict__ hs_unused) {
    const int e    = blockIdx.z;
    const int base = g_off[e];
    const int cnt  = g_off[e + 1] - base;
    const int rowStart = blockIdx.y * 128;
    if (rowStart >= cnt) return;
    const int iStart = blockIdx.x * 128;

    extern __shared__ __align__(1024) char sm[];

    const int tid = threadIdx.x;
    const int wid = tid >> 5, lane = tid & 31;
    // fill mapping: row = tid>>1 (0..127), 4 segs of 16B at col16 = (tid&1)*4 + j
    const int frow = tid >> 1;
    const int fc0  = (tid & 1) * 4;

    const int grow = rowStart + frow;
    const bool av  = (grow < cnt);
    const uint32_t asz = av ? 16u : 0u;
    const int tok  = av ? g_tok[base + grow] : 0;
    const __nv_bfloat16* aph = hs_hi + (size_t)tok * DH;
    const __nv_bfloat16* apl = hs_lo + (size_t)tok * DH;
    const size_t wrow = ((size_t)e * DI + iStart + frow) * DH;
    const __nv_bfloat16* gph = w_g_hi + wrow;
    const __nv_bfloat16* gpl = w_g_lo + wrow;
    const __nv_bfloat16* uph = w_u_hi + wrow;
    const __nv_bfloat16* upl = w_u_lo + wrow;

    const int wm = wid & 3, wn = wid >> 2;
    float accg[2][8][4], accu[2][8][4];
    #pragma unroll
    for (int a = 0; a < 2; a++)
        #pragma unroll
        for (int b = 0; b < 8; b++)
            #pragma unroll
            for (int q = 0; q < 4; q++) { accg[a][b][q] = 0.f; accu[a][b][q] = 0.f; }

    const int a_r = (lane & 15);
    const int a_k = (lane >> 4) * 16;
    const int b_r = ((lane >> 4) & 1) * 8 + (lane & 7);
    const int b_k = ((lane >> 3) & 1) * 16;

    auto fill = [&](int c, char* st) {
        const int k0 = c * KC;
        const uint32_t sb = smem_u32(st);
        #pragma unroll
        for (int j = 0; j < 4; j++) {
            const int col16 = fc0 + j;
            const uint32_t s = SWZ((uint32_t)(frow * 128 + col16 * 16));
            const int ke = k0 + col16 * 8;
            cpa16(sb + s,             aph + ke, asz);
            cpa16(sb + TILEB + s,     apl + ke, asz);
            cpa16(sb + 2 * TILEB + s, gph + ke, 16u);
            cpa16(sb + 3 * TILEB + s, gpl + ke, 16u);
            cpa16(sb + 4 * TILEB + s, uph + ke, 16u);
            cpa16(sb + 5 * TILEB + s, upl + ke, 16u);
        }
    };

    fill(0, sm);
    CP_COMMIT();

    for (int c = 0; c < GU_NCH; c++) {
        if (c + 1 < GU_NCH) {
            fill(c + 1, sm + ((c + 1) & 1) * GU_STAGE);
            CP_COMMIT();
            CP_WAIT(1);
        } else {
            CP_WAIT(0);
        }
        __syncthreads();   // stage c visible to all

        const uint32_t sb = smem_u32(sm + (c & 1) * GU_STAGE);
        const uint32_t sAh = sb, sAl = sb + TILEB;
        const uint32_t sGh = sb + 2 * TILEB, sGl = sb + 3 * TILEB;
        const uint32_t sUh = sb + 4 * TILEB, sUl = sb + 5 * TILEB;

        #pragma unroll
        for (int ks = 0; ks < 4; ks++) {
            uint32_t ah[2][4], al[2][4];
            #pragma unroll
            for (int mi = 0; mi < 2; mi++) {
                uint32_t off = SWZ((uint32_t)((wm * 32 + mi * 16 + a_r) * 128 + ks * 32 + a_k));
                ldm4(ah[mi], sAh + off);
                ldm4(al[mi], sAl + off);
            }
            #pragma unroll
            for (int njp = 0; njp < 4; njp++) {
                uint32_t boff = SWZ((uint32_t)((wn * 64 + njp * 16 + b_r) * 128 + ks * 32 + b_k));
                uint32_t bh[4], bl[4];
                ldm4(bh, sGh + boff);
                ldm4(bl, sGl + boff);
                #pragma unroll
                for (int mi = 0; mi < 2; mi++)
                    #pragma unroll
                    for (int j = 0; j < 2; j++) {
                        mma_bf(accg[mi][njp * 2 + j], ah[mi], &bh[j * 2]);
                        mma_bf(accg[mi][njp * 2 + j], ah[mi], &bl[j * 2]);
                        mma_bf(accg[mi][njp * 2 + j], al[mi], &bh[j * 2]);
                    }
                ldm4(bh, sUh + boff);
                ldm4(bl, sUl + boff);
                #pragma unroll
                for (int mi = 0; mi < 2; mi++)
                    #pragma unroll
                    for (int j = 0; j < 2; j++) {
                        mma_bf(accu[mi][njp * 2 + j], ah[mi], &bh[j * 2]);
                        mma_bf(accu[mi][njp * 2 + j], ah[mi], &bl[j * 2]);
                        mma_bf(accu[mi][njp * 2 + j], al[mi], &bh[j * 2]);
                    }
            }
        }
        __syncthreads();   // all warps done with stage c before it is refilled
    }

    // epilogue: h = w * silu(g) * u, split to bf16 hi/lo in g_h
    #pragma unroll
    for (int mi = 0; mi < 2; mi++) {
        #pragma unroll
        for (int h2 = 0; h2 < 2; h2++) {
            const int r = rowStart + wm * 32 + mi * 16 + (lane >> 2) + h2 * 8;
            if (r < cnt) {
                const float w = g_wt[base + r];
                const size_t rb = (size_t)(base + r) * DI + iStart;
                #pragma unroll
                for (int nj = 0; nj < 8; nj++) {
                    const int col = wn * 64 + nj * 8 + (lane & 3) * 2;
                    float g0 = accg[mi][nj][h2 * 2 + 0], g1 = accg[mi][nj][h2 * 2 + 1];
                    float u0 = accu[mi][nj][h2 * 2 + 0], u1 = accu[mi][nj][h2 * 2 + 1];
                    float h0 = w * (g0 / (1.f + __expf(-g0))) * u0;
                    float h1 = w * (g1 / (1.f + __expf(-g1))) * u1;
                    uint16_t a0, b0, a1, b1;
                    split1(h0, &a0, &b0); split1(h1, &a1, &b1);
                    *(uint32_t*)&g_h_hi[rb + col] = a0 | ((uint32_t)a1 << 16);
                    *(uint32_t*)&g_h_lo[rb + col] = b0 | ((uint32_t)b1 << 16);
                }
            }
        }
    }
}

// ---------------- GEMM 2: down projection -> g_d ------------------------------
#define DN_STAGE (4 * TILEB)
#define DN_SMEM  (2 * DN_STAGE + 64)
#define DN_NCH   (DI / KC)   // 12

__global__ __launch_bounds__(256, 1)
void k_down() {
    const int e    = blockIdx.z;
    const int base = g_off[e];
    const int cnt  = g_off[e + 1] - base;
    const int rowStart = blockIdx.y * 128;
    if (rowStart >= cnt) return;
    const int hStart = blockIdx.x * 128;

    extern __shared__ __align__(1024) char sm[];

    const int tid = threadIdx.x;
    const int wid = tid >> 5, lane = tid & 31;
    const int frow = tid >> 1;
    const int fc0  = (tid & 1) * 4;

    const int grow = rowStart + frow;
    const bool av  = (grow < cnt);
    const uint32_t asz = av ? 16u : 0u;
    const __nv_bfloat16* aph = g_h_hi + (size_t)(av ? base + grow : 0) * DI;
    const __nv_bfloat16* apl = g_h_lo + (size_t)(av ? base + grow : 0) * DI;
    const size_t wrow = ((size_t)e * DH + hStart + frow) * DI;
    const __nv_bfloat16* bph = w_d_hi + wrow;
    const __nv_bfloat16* bpl = w_d_lo + wrow;

    const int wm = wid & 3, wn = wid >> 2;
    float acc[2][8][4];
    #pragma unroll
    for (int a = 0; a < 2; a++)
        #pragma unroll
        for (int b = 0; b < 8; b++)
            #pragma unroll
            for (int q = 0; q < 4; q++) acc[a][b][q] = 0.f;

    const int a_r = (lane & 15);
    const int a_k = (lane >> 4) * 16;
    const int b_r = ((lane >> 4) & 1) * 8 + (lane & 7);
    const int b_k = ((lane >> 3) & 1) * 16;

    auto fill = [&](int c, char* st) {
        const int k0 = c * KC;
        const uint32_t sb = smem_u32(st);
        #pragma unroll
        for (int j = 0; j < 4; j++) {
            const int col16 = fc0 + j;
            const uint32_t s = SWZ((uint32_t)(frow * 128 + col16 * 16));
            const int ke = k0 + col16 * 8;
            cpa16(sb + s,             aph + ke, asz);
            cpa16(sb + TILEB + s,     apl + ke, asz);
            cpa16(sb + 2 * TILEB + s, bph + ke, 16u);
            cpa16(sb + 3 * TILEB + s, bpl + ke, 16u);
        }
    };

    fill(0, sm);
    CP_COMMIT();

    for (int c = 0; c < DN_NCH; c++) {
        if (c + 1 < DN_NCH) {
            fill(c + 1, sm + ((c + 1) & 1) * DN_STAGE);
            CP_COMMIT();
            CP_WAIT(1);
        } else {
            CP_WAIT(0);
        }
        __syncthreads();

        const uint32_t sb = smem_u32(sm + (c & 1) * DN_STAGE);
        const uint32_t sAh = sb, sAl = sb + TILEB;
        const uint32_t sBh = sb + 2 * TILEB, sBl = sb + 3 * TILEB;

        #pragma unroll
        for (int ks = 0; ks < 4; ks++) {
            uint32_t ahf[2][4], alf[2][4];
            #pragma unroll
            for (int mi = 0; mi < 2; mi++) {
                uint32_t off = SWZ((uint32_t)((wm * 32 + mi * 16 + a_r) * 128 + ks * 32 + a_k));
                ldm4(ahf[mi], sAh + off);
                ldm4(alf[mi], sAl + off);
            }
            #pragma unroll
            for (int njp = 0; njp < 4; njp++) {
                uint32_t boff = SWZ((uint32_t)((wn * 64 + njp * 16 + b_r) * 128 + ks * 32 + b_k));
                uint32_t bh[4], bl[4];
                ldm4(bh, sBh + boff);
                ldm4(bl, sBl + boff);
                #pragma unroll
                for (int mi = 0; mi < 2; mi++)
                    #pragma unroll
                    for (int j = 0; j < 2; j++) {
                        mma_bf(acc[mi][njp * 2 + j], ahf[mi], &bh[j * 2]);
                        mma_bf(acc[mi][njp * 2 + j], ahf[mi], &bl[j * 2]);
                        mma_bf(acc[mi][njp * 2 + j], alf[mi], &bh[j * 2]);
                    }
            }
        }
        __syncthreads();
    }

    #pragma unroll
    for (int mi = 0; mi < 2; mi++) {
        #pragma unroll
        for (int h2 = 0; h2 < 2; h2++) {
            const int r = rowStart + wm * 32 + mi * 16 + (lane >> 2) + h2 * 8;
            if (r < cnt) {
                float* dp = &g_d[(size_t)(base + r) * DH + hStart];
                #pragma unroll
                for (int nj = 0; nj < 8; nj++) {
                    const int col = wn * 64 + nj * 8 + (lane & 3) * 2;
                    float2 o;
                    o.x = acc[mi][nj][h2 * 2 + 0];
                    o.y = acc[mi][nj][h2 * 2 + 1];
                    *(float2*)(dp + col) = o;
                }
            }
        }
    }
}

// ---------------- deterministic combine ---------------------------------------
__global__ void k_combine(float* __restrict__ out) {
    const int t = blockIdx.x;
    __shared__ int ps[TOPK];
    if (threadIdx.x < TOPK) ps[threadIdx.x] = g_map[t * TOPK + threadIdx.x];
    __syncthreads();
    const int h = threadIdx.x * 4;
    float4 s = make_float4(0.f, 0.f, 0.f, 0.f);
    #pragma unroll
    for (int k = 0; k < TOPK; k++) {
        float4 v = *(const float4*)&g_d[(size_t)ps[k] * DH + h];
        s.x += v.x; s.y += v.y; s.z += v.z; s.w += v.w;
    }
    *(float4*)&out[(size_t)t * DH + h] = s;
}

// ---------------- launch -------------------------------------------------------
extern "C" void kernel_launch(void* const* d_in, const int* in_sizes, int n_in,
                              void* d_out, int out_size) {
    const float* hs   = (const float*)d_in[0];
    const float* rw   = (const float*)d_in[1];
    const int*   sel  = (const int*)  d_in[2];
    const float* gate = (const float*)d_in[3];
    const float* up   = (const float*)d_in[4];
    const float* down = (const float*)d_in[5];
    float* out = (float*)d_out;

    k_zero<<<1, 32>>>();
    k_count<<<(NP + 255) / 256, 256>>>(sel);
    k_scan<<<1, 1>>>();
    k_scatter<<<(NP + 255) / 256, 256>>>(sel, rw);

    // pre-split fp32 -> bf16 hi/lo
    __nv_bfloat16 *wg_hi, *wg_lo, *wu_hi, *wu_lo, *wd_hi, *wd_lo, *hh, *hl;
    cudaGetSymbolAddress((void**)&wg_hi, w_g_hi);
    cudaGetSymbolAddress((void**)&wg_lo, w_g_lo);
    cudaGetSymbolAddress((void**)&wu_hi, w_u_hi);
    cudaGetSymbolAddress((void**)&wu_lo, w_u_lo);
    cudaGetSymbolAddress((void**)&wd_hi, w_d_hi);
    cudaGetSymbolAddress((void**)&wd_lo, w_d_lo);
    cudaGetSymbolAddress((void**)&hh, hs_hi);
    cudaGetSymbolAddress((void**)&hl, hs_lo);

    const int nw8 = NW / 8;
    k_cvt<<<(nw8 + 255) / 256, 256>>>(gate, wg_hi, wg_lo, nw8);
    k_cvt<<<(nw8 + 255) / 256, 256>>>(up,   wu_hi, wu_lo, nw8);
    k_cvt<<<(nw8 + 255) / 256, 256>>>(down, wd_hi, wd_lo, nw8);
    const int nh8 = NT * DH / 8;
    k_cvt<<<(nh8 + 255) / 256, 256>>>(hs, hh, hl, nh8);

    cudaFuncSetAttribute(k_gateup, cudaFuncAttributeMaxDynamicSharedMemorySize, GU_SMEM);
    cudaFuncSetAttribute(k_down,   cudaFuncAttributeMaxDynamicSharedMemorySize, DN_SMEM);

    dim3 gg(DI / 128, 16, NE);   // (6, 16, 32) — token tiles early-exit
    k_gateup<<<gg, 256, GU_SMEM>>>(hs);

    dim3 gd(DH / 128, 16, NE);   // (8, 16, 32)
    k_down<<<gd, 256, DN_SMEM>>>();

    k_combine<<<NT, 256>>>(out);
}